// round 15
// baseline (speedup 1.0000x reference)
#include <cuda_runtime.h>
#include <cuda.h>
#include <cuda_fp16.h>
#include <math.h>
#include <stdint.h>

// Problem constants
#define BATCH 8
#define SEQ   1024
#define CH    768
#define C3    2304      // 3*CH
#define C6    4608      // 6*CH
#define HFDIM 3072      // 4*CH
#define NHEAD 12
#define HDIM  64
#define ROWS  8192      // BATCH*SEQ

// ---------------------------------------------------------------------------
// Scratch (device globals — no allocation allowed)
// ---------------------------------------------------------------------------
__device__ float g_ada[BATCH * C6];
__device__ float g_x1 [(size_t)ROWS * CH];
__device__ __half g_hb  [(size_t)ROWS * CH];
__device__ __half g_qkvh[(size_t)ROWS * C3];
__device__ __half g_attb[(size_t)ROWS * CH];
__device__ __half g_mlph[(size_t)ROWS * HFDIM];
__device__ __half g_wqkv[(size_t)C3 * CH];
__device__ __half g_wproj[(size_t)CH * CH];
__device__ __half g_wfc1[(size_t)HFDIM * CH];
__device__ __half g_wfc2[(size_t)CH * HFDIM];

// ---------------------------------------------------------------------------
// PTX helpers
// ---------------------------------------------------------------------------
__device__ __forceinline__ uint32_t smem_to_u32(const void* p) {
    uint32_t a;
    asm("{ .reg .u64 t; cvta.to.shared.u64 t, %1; cvt.u32.u64 %0, t; }"
        : "=r"(a) : "l"(p));
    return a;
}

#define MBARRIER_INIT(addr, cnt) \
    asm volatile("mbarrier.init.shared.b64 [%0], %1;" :: "r"((uint32_t)(addr)), "r"((uint32_t)(cnt)) : "memory")

#define MBARRIER_ARRIVE(addr) \
    asm volatile("mbarrier.arrive.shared.b64 _, [%0];" :: "r"((uint32_t)(addr)) : "memory")

#define MBARRIER_EXPECT_TX(addr, bytes) \
    asm volatile("mbarrier.arrive.expect_tx.shared.b64 _, [%0], %1;" :: "r"((uint32_t)(addr)), "r"((uint32_t)(bytes)) : "memory")

#define MBARRIER_WAIT_PARITY(mbar_smem_addr, phase_parity) do { \
    uint32_t _mbar = (uint32_t)(mbar_smem_addr); \
    uint32_t _parity = (uint32_t)(phase_parity); \
    uint32_t _done; \
    asm volatile( \
        "{\n\t.reg .pred p;\n\t" \
        "mbarrier.try_wait.parity.acquire.cta.shared::cta.b64 p, [%1], %2;\n\t" \
        "selp.b32 %0, 1, 0, p;\n\t}" \
        : "=r"(_done) : "r"(_mbar), "r"(_parity) : "memory"); \
    if (!_done) { \
        asm volatile( \
            "{\n\t.reg .pred P1;\n\t" \
            "WAIT_LOOP_%=:\n\t" \
            "mbarrier.try_wait.parity.acquire.cta.shared::cta.b64 P1, [%0], %1, 0x989680;\n\t" \
            "@P1 bra.uni WAIT_DONE_%=;\n\t" \
            "bra.uni WAIT_LOOP_%=;\n\t" \
            "WAIT_DONE_%=:\n\t}" \
            :: "r"(_mbar), "r"(_parity) : "memory"); \
    } \
} while(0)

#define MBARRIER_WAIT_PARITY_RELAXED(mbar_smem_addr, phase_parity) do { \
    uint32_t _mbar = (uint32_t)(mbar_smem_addr); \
    uint32_t _parity = (uint32_t)(phase_parity); \
    uint32_t _done; \
    asm volatile( \
        "{\n\t.reg .pred p;\n\t" \
        "mbarrier.try_wait.parity.relaxed.cta.shared::cta.b64 p, [%1], %2, 0x989680;\n\t" \
        "selp.b32 %0, 1, 0, p;\n\t}" \
        : "=r"(_done) : "r"(_mbar), "r"(_parity) : "memory"); \
    if (!_done) { \
        asm volatile( \
            "{\n\t.reg .pred P1;\n\t" \
            "WAIT_LOOP_%=:\n\t" \
            "mbarrier.try_wait.parity.relaxed.cta.shared::cta.b64 P1, [%0], %1, 0x989680;\n\t" \
            "@P1 bra.uni WAIT_DONE_%=;\n\t" \
            "bra.uni WAIT_LOOP_%=;\n\t" \
            "WAIT_DONE_%=:\n\t}" \
            :: "r"(_mbar), "r"(_parity) : "memory"); \
    } \
} while(0)

__device__ __forceinline__ void ldsm_x4(uint32_t* r, uint32_t addr) {
    asm volatile("ldmatrix.sync.aligned.m8n8.x4.shared.b16 {%0,%1,%2,%3}, [%4];"
        : "=r"(r[0]), "=r"(r[1]), "=r"(r[2]), "=r"(r[3]) : "r"(addr));
}
__device__ __forceinline__ void ldsm_x4_t(uint32_t* r, uint32_t addr) {
    asm volatile("ldmatrix.sync.aligned.m8n8.x4.trans.shared.b16 {%0,%1,%2,%3}, [%4];"
        : "=r"(r[0]), "=r"(r[1]), "=r"(r[2]), "=r"(r[3]) : "r"(addr));
}

__device__ __forceinline__ void mma_f16(float* c, const uint32_t* a, uint32_t b0, uint32_t b1) {
    asm volatile(
        "mma.sync.aligned.m16n8k16.row.col.f32.f16.f16.f32 "
        "{%0,%1,%2,%3}, {%4,%5,%6,%7}, {%8,%9}, {%0,%1,%2,%3};"
        : "+f"(c[0]), "+f"(c[1]), "+f"(c[2]), "+f"(c[3])
        : "r"(a[0]), "r"(a[1]), "r"(a[2]), "r"(a[3]), "r"(b0), "r"(b1));
}

// pack (lo, hi) floats into f16x2
__device__ __forceinline__ uint32_t pack_f16(float lo, float hi) {
    uint32_t d;
    asm("cvt.rn.f16x2.f32 %0, %1, %2;" : "=r"(d) : "f"(hi), "f"(lo));
    return d;
}

// single-MUFU 2^x
__device__ __forceinline__ float ex2(float x) {
    float y;
    asm("ex2.approx.ftz.f32 %0, %1;" : "=f"(y) : "f"(x));
    return y;
}

__device__ __forceinline__ void cpasync16(uint32_t dst, const void* src) {
    asm volatile("cp.async.cg.shared.global [%0], [%1], 16;" :: "r"(dst), "l"(src) : "memory");
}
#define CPASYNC_COMMIT() asm volatile("cp.async.commit_group;" ::: "memory")
#define CPASYNC_WAIT0()  asm volatile("cp.async.wait_group 0;" ::: "memory")

// ---------------------------------------------------------------------------
// 0) Merged: fp32->fp16 weight conversion + ada = silu(c) @ ada_w^T + ada_b
// ---------------------------------------------------------------------------
#define CVT_N1 (C3 * CH / 4)
#define CVT_N2 (CVT_N1 + CH * CH / 4)
#define CVT_N3 (CVT_N2 + HFDIM * CH / 4)
#define CVT_N4 (CVT_N3 + CH * HFDIM / 4)
#define CVT_BLOCKS ((CVT_N4 + 255) / 256)
#define ADA_BLOCKS (BATCH * (C6 / 8))          // 8 x 576

__global__ __launch_bounds__(256) void cvt_ada_kernel(
    const float* __restrict__ s0, const float* __restrict__ s1,
    const float* __restrict__ s2, const float* __restrict__ s3,
    const float* __restrict__ c,
    const float* __restrict__ ada_w,
    const float* __restrict__ ada_b)
{
    __shared__ float sc[CH];
    int bid = blockIdx.x;
    if (bid < CVT_BLOCKS) {
        int i = bid * 256 + threadIdx.x;
        if (i >= CVT_N4) return;
        const float* src; __half* dst; int off;
        if (i < CVT_N1)      { src = s0; dst = g_wqkv;  off = i; }
        else if (i < CVT_N2) { src = s1; dst = g_wproj; off = i - CVT_N1; }
        else if (i < CVT_N3) { src = s2; dst = g_wfc1;  off = i - CVT_N2; }
        else                 { src = s3; dst = g_wfc2;  off = i - CVT_N3; }
        float4 v = *(const float4*)(src + (size_t)off * 4);
        uint32_t* d = (uint32_t*)dst + (size_t)off * 2;
        d[0] = pack_f16(v.x, v.y);
        d[1] = pack_f16(v.z, v.w);
        return;
    }
    // ada part
    int abid = bid - CVT_BLOCKS;       // 0 .. ADA_BLOCKS-1
    int b = abid / (C6 / 8);
    int jb = abid % (C6 / 8);
    for (int k = threadIdx.x; k < CH; k += 256) {
        float v = c[b * CH + k];
        sc[k] = v / (1.f + expf(-v));
    }
    __syncthreads();
    int warp = threadIdx.x >> 5, lane = threadIdx.x & 31;
    int j = jb * 8 + warp;
    const float* w = ada_w + (size_t)j * CH;
    float s = 0.f;
    for (int k = lane; k < CH; k += 32) s += sc[k] * w[k];
#pragma unroll
    for (int o = 16; o; o >>= 1) s += __shfl_xor_sync(0xffffffffu, s, o);
    if (lane == 0) g_ada[b * C6 + j] = s + ada_b[j];
}

// ---------------------------------------------------------------------------
// 2) h = LN(x) * (1 + sc[b]) + sh[b]   -> fp16.  One warp per row.
// ---------------------------------------------------------------------------
__global__ __launch_bounds__(256) void ln_mod_kernel(
    const float* __restrict__ x, int sh_off, int sc_off,
    __half* __restrict__ out)
{
    int r = blockIdx.x * 8 + (threadIdx.x >> 5);
    int lane = threadIdx.x & 31;
    int b = r >> 10;
    const float* xr = x + (size_t)r * CH;

    float4 v[6];
    float s = 0.f, ss = 0.f;
#pragma unroll
    for (int u = 0; u < 6; u++) {
        v[u] = *(const float4*)(xr + lane * 4 + u * 128);
        s  += v[u].x + v[u].y + v[u].z + v[u].w;
        ss += v[u].x * v[u].x + v[u].y * v[u].y + v[u].z * v[u].z + v[u].w * v[u].w;
    }
#pragma unroll
    for (int o = 16; o; o >>= 1) {
        s  += __shfl_xor_sync(0xffffffffu, s,  o);
        ss += __shfl_xor_sync(0xffffffffu, ss, o);
    }
    float mu  = s  * (1.f / (float)CH);
    float var = ss * (1.f / (float)CH) - mu * mu;
    float rinv = rsqrtf(var + 1e-6f);

    const float* sh  = g_ada + b * C6 + sh_off;
    const float* scm = g_ada + b * C6 + sc_off;
    uint32_t* orow = (uint32_t*)(out + (size_t)r * CH);
#pragma unroll
    for (int u = 0; u < 6; u++) {
        int i = lane * 4 + u * 128;
        float4 sh4  = *(const float4*)(sh + i);
        float4 sc4  = *(const float4*)(scm + i);
        float o0 = (v[u].x - mu) * rinv * (1.f + sc4.x) + sh4.x;
        float o1 = (v[u].y - mu) * rinv * (1.f + sc4.y) + sh4.y;
        float o2 = (v[u].z - mu) * rinv * (1.f + sc4.z) + sh4.z;
        float o3 = (v[u].w - mu) * rinv * (1.f + sc4.w) + sh4.w;
        orow[(i >> 1) + 0] = pack_f16(o0, o1);
        orow[(i >> 1) + 1] = pack_f16(o2, o3);
    }
}

// ---------------------------------------------------------------------------
// 3) TMA + mma.sync fp16 GEMM: 128x128 tile, 3-stage pipeline, 2 CTAs/SM.
//    160 threads: warps 0-3 compute (64x64 each, 2x2), warp 4 = TMA producer.
//    EPI: 0 = bias -> fp16; 1 = bias+GELU -> fp16; 2 = resid+gate -> fp32
// ---------------------------------------------------------------------------
#define GSTAGES 3
#define STAGE_BYTES 32768            // A 16KB + B 16KB
#define GEMM_SMEM (1024 + GSTAGES * STAGE_BYTES)   // 99328

// swizzled address in [rows x 128B] SW128 tile, chunk = 16B unit
__device__ __forceinline__ uint32_t gsw(uint32_t base, int row, int chunk) {
    return base + row * 128 + ((chunk ^ (row & 7)) << 4);
}

template <int EPI>
__global__ __launch_bounds__(160, 2) void tc_gemm_kernel(
    const __grid_constant__ CUtensorMap tmA,
    const __grid_constant__ CUtensorMap tmB,
    const float* __restrict__ bias,
    const float* __restrict__ resid,
    const float* __restrict__ gate,
    void* __restrict__ CoutV,
    int Nc, int K)
{
    extern __shared__ __align__(1024) char smem[];
    uint32_t sbase = smem_to_u32(smem);
    const int t = threadIdx.x, wid = t >> 5, lane = t & 31;
    const int m0 = blockIdx.y * 128, n0 = blockIdx.x * 128;
    const int KT = K / 64;

    const uint32_t mb_full  = sbase + 0;
    const uint32_t mb_empty = sbase + 64;
    const uint32_t stg = sbase + 1024;

    if (t == 0) {
#pragma unroll
        for (int s = 0; s < GSTAGES; s++) {
            MBARRIER_INIT(mb_full  + 8 * s, 1);
            MBARRIER_INIT(mb_empty + 8 * s, 4);
        }
    }
    __syncthreads();

    if (wid == 4) {
        if (lane == 0) {
            asm volatile("prefetch.tensormap [%0];" :: "l"(&tmA));
            asm volatile("prefetch.tensormap [%0];" :: "l"(&tmB));
            int npro = KT < GSTAGES ? KT : GSTAGES;
            for (int tt = 0; tt < npro; tt++) {
                uint32_t fm = mb_full + 8 * tt;
                uint32_t aA = stg + tt * STAGE_BYTES;
                MBARRIER_EXPECT_TX(fm, STAGE_BYTES);
                int k0 = tt * 64;
                asm volatile(
                    "cp.async.bulk.tensor.2d.shared::cta.global.tile.mbarrier::complete_tx::bytes "
                    "[%0], [%1, {%2, %3}], [%4];"
                    :: "r"(aA), "l"(&tmA), "r"(k0), "r"(m0), "r"(fm) : "memory");
                asm volatile(
                    "cp.async.bulk.tensor.2d.shared::cta.global.tile.mbarrier::complete_tx::bytes "
                    "[%0], [%1, {%2, %3}], [%4];"
                    :: "r"(aA + 16384), "l"(&tmB), "r"(k0), "r"(n0), "r"(fm) : "memory");
            }
            int slot = 0, ph = 0;
            for (int tt = GSTAGES; tt < KT; tt++) {
                MBARRIER_WAIT_PARITY_RELAXED(mb_empty + 8 * slot, ph);
                uint32_t fm = mb_full + 8 * slot;
                uint32_t aA = stg + slot * STAGE_BYTES;
                MBARRIER_EXPECT_TX(fm, STAGE_BYTES);
                int k0 = tt * 64;
                asm volatile(
                    "cp.async.bulk.tensor.2d.shared::cta.global.tile.mbarrier::complete_tx::bytes "
                    "[%0], [%1, {%2, %3}], [%4];"
                    :: "r"(aA), "l"(&tmA), "r"(k0), "r"(m0), "r"(fm) : "memory");
                asm volatile(
                    "cp.async.bulk.tensor.2d.shared::cta.global.tile.mbarrier::complete_tx::bytes "
                    "[%0], [%1, {%2, %3}], [%4];"
                    :: "r"(aA + 16384), "l"(&tmB), "r"(k0), "r"(n0), "r"(fm) : "memory");
                if (++slot == GSTAGES) { slot = 0; ph ^= 1; }
            }
        }
        return;
    }

    const int wm = wid >> 1;          // 0..1
    const int wn = wid & 1;           // 0..1
    const int g   = lane >> 2;
    const int ctg = lane & 3;
    const int lrow = (lane & 7) + 8 * ((lane >> 3) & 1);
    const int lch  = lane >> 4;

    float acc[4][8][4];
#pragma unroll
    for (int im = 0; im < 4; im++)
#pragma unroll
        for (int in = 0; in < 8; in++)
#pragma unroll
            for (int r = 0; r < 4; r++) acc[im][in][r] = 0.f;

    int slot = 0, ph = 0;
    for (int tt = 0; tt < KT; tt++) {
        MBARRIER_WAIT_PARITY(mb_full + 8 * slot, ph);
        const uint32_t At = stg + slot * STAGE_BYTES;
        const uint32_t Bt = At + 16384;

#pragma unroll
        for (int s = 0; s < 4; s++) {            // k16 steps
            const int kc = 2 * s;
            uint32_t afr[4][4];
#pragma unroll
            for (int im = 0; im < 4; im++)
                ldsm_x4(afr[im], gsw(At, wm * 64 + im * 16 + lrow, kc + lch));
            uint32_t bfr[8][2];
#pragma unroll
            for (int jn = 0; jn < 4; jn++) {
                uint32_t q[4];
                ldsm_x4(q, gsw(Bt, wn * 64 + jn * 16 + lrow, kc + lch));
                bfr[2 * jn][0]     = q[0]; bfr[2 * jn][1]     = q[2];
                bfr[2 * jn + 1][0] = q[1]; bfr[2 * jn + 1][1] = q[3];
            }
#pragma unroll
            for (int im = 0; im < 4; im++)
#pragma unroll
                for (int in = 0; in < 8; in++)
                    mma_f16(acc[im][in], afr[im], bfr[in][0], bfr[in][1]);
        }

        if (lane == 0) MBARRIER_ARRIVE(mb_empty + 8 * slot);
        if (++slot == GSTAGES) { slot = 0; ph ^= 1; }
    }

    // epilogue
    const int bidx = m0 >> 10;        // tiles never straddle a batch
    const int mB = m0 + wm * 64;
    const int nB = n0 + wn * 64;
#pragma unroll
    for (int im = 0; im < 4; im++) {
        int r = mB + im * 16 + g;
#pragma unroll
        for (int in = 0; in < 8; in++) {
            int n = nB + in * 8 + 2 * ctg;
            float b0 = bias[n], b1 = bias[n + 1];
#pragma unroll
            for (int half = 0; half < 2; half++) {
                int m = r + half * 8;
                float v0 = acc[im][in][2 * half + 0] + b0;
                float v1 = acc[im][in][2 * half + 1] + b1;
                if (EPI == 1) {
                    v0 = 0.5f * v0 * (1.f + erff(v0 * 0.70710678118654752f));
                    v1 = 0.5f * v1 * (1.f + erff(v1 * 0.70710678118654752f));
                }
                if (EPI == 2) {
                    const float2 rr = *(const float2*)&resid[(size_t)m * Nc + n];
                    float g0 = gate[bidx * C6 + n], g1 = gate[bidx * C6 + n + 1];
                    v0 = rr.x + g0 * v0;
                    v1 = rr.y + g1 * v1;
                    *(float2*)&((float*)CoutV)[(size_t)m * Nc + n] = make_float2(v0, v1);
                } else {
                    ((uint32_t*)CoutV)[((size_t)m * Nc + n) >> 1] = pack_f16(v0, v1);
                }
            }
        }
    }
}

// ---------------------------------------------------------------------------
// 4) fp16 flash attention: 128 q-rows per CTA (8 warps), K/V 64-row tiles
//    double-buffered via cp.async, P in registers, exp2 softmax (MUFU).
// ---------------------------------------------------------------------------
#define AT_WB 144                        // tile row stride in bytes
#define AT_TILE_B (64 * AT_WB)           // K/V tile: 64 rows
#define AQ_TILE_B (128 * AT_WB)          // Q tile: 128 rows
#define ATT_SMEM (AQ_TILE_B + 4 * AT_TILE_B)   // 55296

__global__ __launch_bounds__(256, 2) void attn_tc_kernel(
    const __half* __restrict__ qkv, __half* __restrict__ out)
{
    extern __shared__ __align__(16) char as[];
    const uint32_t Qb = smem_to_u32(as);
    const uint32_t Kb = Qb + AQ_TILE_B;
    const uint32_t Vb = Kb + 2 * AT_TILE_B;

    const int b = blockIdx.z, h = blockIdx.y;
    const int q0 = blockIdx.x * 128;
    const int t = threadIdx.x, wq = t >> 5, lane = t & 31;
    const int g = lane >> 2, ctg = lane & 3;
    const int lrow = (lane & 7) + 8 * ((lane >> 3) & 1);
    const int lch  = lane >> 4;

    const __half* qb = qkv + (size_t)(b * SEQ) * C3 + h * HDIM;
    const __half* kb = qb + CH;
    const __half* vb = qb + 2 * CH;

    const float cs = 0.18033688f;        // 0.125 * log2(e)

    // Q tile: 128 rows x 8 chunks = 1024 chunks, 4 per thread
#pragma unroll
    for (int u = 0; u < 4; u++) {
        int i = t + u * 256;
        int r = i >> 3, c = i & 7;
        cpasync16(Qb + (uint32_t)(r * AT_WB + c * 16),
                  qb + (size_t)(q0 + r) * C3 + c * 8);
    }
    // K/V tile 0: 64 rows x 8 chunks = 512 chunks, 2 per thread each
#pragma unroll
    for (int u = 0; u < 2; u++) {
        int i = t + u * 256;
        int r = i >> 3, c = i & 7;
        uint32_t so = (uint32_t)(r * AT_WB + c * 16);
        cpasync16(Kb + so, kb + (size_t)r * C3 + c * 8);
        cpasync16(Vb + so, vb + (size_t)r * C3 + c * 8);
    }
    CPASYNC_COMMIT();

    float m0 = -1e30f, m1 = -1e30f, l0 = 0.f, l1 = 0.f;
    float oac[8][4];
#pragma unroll
    for (int in = 0; in < 8; in++)
#pragma unroll
        for (int r = 0; r < 4; r++) oac[in][r] = 0.f;

    uint32_t qf[4][4];

    for (int kt = 0; kt < 16; kt++) {
        CPASYNC_WAIT0();
        __syncthreads();
        if (kt == 0) {
#pragma unroll
            for (int kk = 0; kk < 4; kk++)
                ldsm_x4(qf[kk], Qb + (wq * 16 + lrow) * AT_WB + (2 * kk + lch) * 16);
        }
        if (kt + 1 < 16) {
            int nb = (kt + 1) & 1;
            int kr0 = (kt + 1) * 64;
            uint32_t kd = Kb + nb * AT_TILE_B;
            uint32_t vd = Vb + nb * AT_TILE_B;
#pragma unroll
            for (int u = 0; u < 2; u++) {
                int i = t + u * 256;
                int r = i >> 3, c = i & 7;
                uint32_t so = (uint32_t)(r * AT_WB + c * 16);
                cpasync16(kd + so, kb + (size_t)(kr0 + r) * C3 + c * 8);
                cpasync16(vd + so, vb + (size_t)(kr0 + r) * C3 + c * 8);
            }
            CPASYNC_COMMIT();
        }

        const uint32_t Kt = Kb + (kt & 1) * AT_TILE_B;
        const uint32_t Vt = Vb + (kt & 1) * AT_TILE_B;

        // S = Q @ K^T (raw, scale folded into softmax)
        float sac[8][4];
#pragma unroll
        for (int in = 0; in < 8; in++)
#pragma unroll
            for (int r = 0; r < 4; r++) sac[in][r] = 0.f;

#pragma unroll
        for (int kk = 0; kk < 4; kk++) {
            const int kc = 2 * kk;
#pragma unroll
            for (int jn = 0; jn < 4; jn++) {
                uint32_t q[4];
                ldsm_x4(q, Kt + (jn * 16 + lrow) * AT_WB + (kc + lch) * 16);
                mma_f16(sac[2 * jn],     qf[kk], q[0], q[2]);
                mma_f16(sac[2 * jn + 1], qf[kk], q[1], q[3]);
            }
        }

        // online softmax in log2 domain (rows g, g+8)
        float mx0 = -1e30f, mx1 = -1e30f;
#pragma unroll
        for (int in = 0; in < 8; in++) {
            mx0 = fmaxf(mx0, fmaxf(sac[in][0], sac[in][1]));
            mx1 = fmaxf(mx1, fmaxf(sac[in][2], sac[in][3]));
        }
        mx0 = fmaxf(mx0, __shfl_xor_sync(0xffffffffu, mx0, 1));
        mx0 = fmaxf(mx0, __shfl_xor_sync(0xffffffffu, mx0, 2));
        mx1 = fmaxf(mx1, __shfl_xor_sync(0xffffffffu, mx1, 1));
        mx1 = fmaxf(mx1, __shfl_xor_sync(0xffffffffu, mx1, 2));

        float mn0 = fmaxf(m0, mx0 * cs), mn1 = fmaxf(m1, mx1 * cs);
        float a0 = ex2(m0 - mn0), a1 = ex2(m1 - mn1);
        float s0 = 0.f, s1 = 0.f;
#pragma unroll
        for (int in = 0; in < 8; in++) {
            sac[in][0] = ex2(fmaf(sac[in][0], cs, -mn0));
            sac[in][1] = ex2(fmaf(sac[in][1], cs, -mn0));
            sac[in][2] = ex2(fmaf(sac[in][2], cs, -mn1));
            sac[in][3] = ex2(fmaf(sac[in][3], cs, -mn1));
            s0 += sac[in][0] + sac[in][1];
            s1 += sac[in][2] + sac[in][3];
        }
        s0 += __shfl_xor_sync(0xffffffffu, s0, 1);
        s0 += __shfl_xor_sync(0xffffffffu, s0, 2);
        s1 += __shfl_xor_sync(0xffffffffu, s1, 1);
        s1 += __shfl_xor_sync(0xffffffffu, s1, 2);
        l0 = l0 * a0 + s0; m0 = mn0;
        l1 = l1 * a1 + s1; m1 = mn1;
#pragma unroll
        for (int in = 0; in < 8; in++) {
            oac[in][0] *= a0; oac[in][1] *= a0;
            oac[in][2] *= a1; oac[in][3] *= a1;
        }

        // O += P @ V (P packed to fp16 in registers)
#pragma unroll
        for (int kk = 0; kk < 4; kk++) {
            uint32_t pf[4];
            pf[0] = pack_f16(sac[2 * kk][0],     sac[2 * kk][1]);
            pf[1] = pack_f16(sac[2 * kk][2],     sac[2 * kk][3]);
            pf[2] = pack_f16(sac[2 * kk + 1][0], sac[2 * kk + 1][1]);
            pf[3] = pack_f16(sac[2 * kk + 1][2], sac[2 * kk + 1][3]);
            const int vrow = 16 * kk + (lane & 7) + 8 * (lane >> 4);
#pragma unroll
            for (int jn = 0; jn < 4; jn++) {
                uint32_t q[4];
                ldsm_x4_t(q, Vt + vrow * AT_WB + (2 * jn + ((lane >> 3) & 1)) * 16);
                mma_f16(oac[2 * jn],     pf, q[0], q[2]);
                mma_f16(oac[2 * jn + 1], pf, q[1], q[3]);
            }
        }
        // no bottom barrier needed: next iteration's wait+sync orders buffer reuse
    }

    // write O (fp16)
    float inv0 = 1.f / l0, inv1 = 1.f / l1;
    int row0 = b * SEQ + q0 + wq * 16 + g;
    uint32_t* o32 = (uint32_t*)out;
#pragma unroll
    for (int in = 0; in < 8; in++) {
        int col = h * HDIM + in * 8 + 2 * ctg;
        o32[((size_t)row0 * CH + col) >> 1] =
            pack_f16(oac[in][0] * inv0, oac[in][1] * inv0);
        o32[((size_t)(row0 + 8) * CH + col) >> 1] =
            pack_f16(oac[in][2] * inv1, oac[in][3] * inv1);
    }
}

// ---------------------------------------------------------------------------
// Host: tensormap construction
// ---------------------------------------------------------------------------
typedef CUresult (*PFN_tmEncode)(
    CUtensorMap*, CUtensorMapDataType, cuuint32_t, void*,
    const cuuint64_t*, const cuuint64_t*, const cuuint32_t*, const cuuint32_t*,
    CUtensorMapInterleave, CUtensorMapSwizzle, CUtensorMapL2promotion,
    CUtensorMapFloatOOBfill);

static PFN_tmEncode get_tm_encode() {
    void* fn = nullptr;
#if CUDART_VERSION >= 12050
    cudaDriverEntryPointQueryResult qr;
    cudaGetDriverEntryPointByVersion("cuTensorMapEncodeTiled", &fn, 12000,
                                     cudaEnableDefault, &qr);
#else
    cudaDriverEntryPointQueryResult qr;
    cudaGetDriverEntryPoint("cuTensorMapEncodeTiled", &fn, cudaEnableDefault, &qr);
#endif
    return (PFN_tmEncode)fn;
}

static void make_tm_f16(PFN_tmEncode enc, CUtensorMap* tm, const void* p, int K, int M) {
    cuuint64_t dims[2]    = {(cuuint64_t)K, (cuuint64_t)M};
    cuuint64_t strides[1] = {(cuuint64_t)K * 2};
    cuuint32_t box[2]     = {64u, 128u};
    cuuint32_t es[2]      = {1u, 1u};
    enc(tm, CU_TENSOR_MAP_DATA_TYPE_FLOAT16, 2, (void*)p, dims, strides, box, es,
        CU_TENSOR_MAP_INTERLEAVE_NONE, CU_TENSOR_MAP_SWIZZLE_128B,
        CU_TENSOR_MAP_L2_PROMOTION_L2_128B, CU_TENSOR_MAP_FLOAT_OOB_FILL_NONE);
}

// ---------------------------------------------------------------------------
// Launch
// ---------------------------------------------------------------------------
extern "C" void kernel_launch(void* const* d_in, const int* in_sizes, int n_in,
                              void* d_out, int out_size)
{
    const float* x      = (const float*)d_in[0];
    const float* c      = (const float*)d_in[1];
    const float* qkv_w  = (const float*)d_in[2];
    const float* qkv_b  = (const float*)d_in[3];
    const float* proj_w = (const float*)d_in[4];
    const float* proj_b = (const float*)d_in[5];
    const float* fc1_w  = (const float*)d_in[6];
    const float* fc1_b  = (const float*)d_in[7];
    const float* fc2_w  = (const float*)d_in[8];
    const float* fc2_b  = (const float*)d_in[9];
    const float* ada_w  = (const float*)d_in[10];
    const float* ada_b  = (const float*)d_in[11];
    float* out = (float*)d_out;

    float *p_ada, *p_x1;
    __half *p_hb, *p_qkvh, *p_attb, *p_mlph, *p_wqkv, *p_wproj, *p_wfc1, *p_wfc2;
    cudaGetSymbolAddress((void**)&p_ada,   g_ada);
    cudaGetSymbolAddress((void**)&p_x1,    g_x1);
    cudaGetSymbolAddress((void**)&p_hb,    g_hb);
    cudaGetSymbolAddress((void**)&p_qkvh,  g_qkvh);
    cudaGetSymbolAddress((void**)&p_attb,  g_attb);
    cudaGetSymbolAddress((void**)&p_mlph,  g_mlph);
    cudaGetSymbolAddress((void**)&p_wqkv,  g_wqkv);
    cudaGetSymbolAddress((void**)&p_wproj, g_wproj);
    cudaGetSymbolAddress((void**)&p_wfc1,  g_wfc1);
    cudaGetSymbolAddress((void**)&p_wfc2,  g_wfc2);

    PFN_tmEncode enc = get_tm_encode();
    alignas(64) CUtensorMap tm_h, tm_att, tm_mlp, tm_qkvw, tm_projw, tm_fc1w, tm_fc2w;
    make_tm_f16(enc, &tm_h,     p_hb,    CH,    ROWS);
    make_tm_f16(enc, &tm_att,   p_attb,  CH,    ROWS);
    make_tm_f16(enc, &tm_mlp,   p_mlph,  HFDIM, ROWS);
    make_tm_f16(enc, &tm_qkvw,  p_wqkv,  CH,    C3);
    make_tm_f16(enc, &tm_projw, p_wproj, CH,    CH);
    make_tm_f16(enc, &tm_fc1w,  p_wfc1,  CH,    HFDIM);
    make_tm_f16(enc, &tm_fc2w,  p_wfc2,  HFDIM, CH);

    cudaFuncSetAttribute((const void*)tc_gemm_kernel<0>, cudaFuncAttributeMaxDynamicSharedMemorySize, GEMM_SMEM);
    cudaFuncSetAttribute((const void*)tc_gemm_kernel<1>, cudaFuncAttributeMaxDynamicSharedMemorySize, GEMM_SMEM);
    cudaFuncSetAttribute((const void*)tc_gemm_kernel<2>, cudaFuncAttributeMaxDynamicSharedMemorySize, GEMM_SMEM);
    cudaFuncSetAttribute((const void*)attn_tc_kernel, cudaFuncAttributeMaxDynamicSharedMemorySize, ATT_SMEM);

    // 0) weight conversion + adaLN parameters (one launch)
    cvt_ada_kernel<<<CVT_BLOCKS + ADA_BLOCKS, 256>>>(
        qkv_w, proj_w, fc1_w, fc2_w, c, ada_w, ada_b);

    // 2) h = modulate(LN(x), sh_msa, sc_msa) -> fp16
    ln_mod_kernel<<<ROWS / 8, 256>>>(x, 0, 768, p_hb);

    // 3) qkv = h @ qkv_w^T + qkv_b -> fp16
    tc_gemm_kernel<0><<<dim3(C3 / 128, ROWS / 128), 160, GEMM_SMEM>>>(
        tm_h, tm_qkvw, qkv_b, nullptr, nullptr, p_qkvh, C3, CH);

    // 4) attention -> fp16
    attn_tc_kernel<<<dim3(SEQ / 128, NHEAD, BATCH), 256, ATT_SMEM>>>(p_qkvh, p_attb);

    // 5) x1 = x + g_msa * (attn @ proj_w^T + proj_b) -> fp32
    tc_gemm_kernel<2><<<dim3(CH / 128, ROWS / 128), 160, GEMM_SMEM>>>(
        tm_att, tm_projw, proj_b, x, p_ada + 1536, p_x1, CH, CH);

    // 6) h = modulate(LN(x1), sh_mlp, sc_mlp) -> fp16
    ln_mod_kernel<<<ROWS / 8, 256>>>(p_x1, 2304, 3072, p_hb);

    // 7) mlp_hidden = gelu(h @ fc1_w^T + fc1_b) -> fp16
    tc_gemm_kernel<1><<<dim3(HFDIM / 128, ROWS / 128), 160, GEMM_SMEM>>>(
        tm_h, tm_fc1w, fc1_b, nullptr, nullptr, p_mlph, HFDIM, CH);

    // 8) out = x1 + g_mlp * (mlp_hidden @ fc2_w^T + fc2_b) -> fp32
    tc_gemm_kernel<2><<<dim3(CH / 128, ROWS / 128), 160, GEMM_SMEM>>>(
        tm_mlp, tm_fc2w, fc2_b, p_x1, p_ada + 3840, out, CH, HFDIM);
}

// round 17
// speedup vs baseline: 1.0941x; 1.0941x over previous
#include <cuda_runtime.h>
#include <cuda.h>
#include <cuda_fp16.h>
#include <math.h>
#include <stdint.h>

// Problem constants
#define BATCH 8
#define SEQ   1024
#define CH    768
#define C3    2304      // 3*CH
#define C6    4608      // 6*CH
#define HFDIM 3072      // 4*CH
#define NHEAD 12
#define HDIM  64
#define ROWS  8192      // BATCH*SEQ

// ---------------------------------------------------------------------------
// Scratch (device globals — no allocation allowed)
// ---------------------------------------------------------------------------
__device__ float g_ada[BATCH * C6];
__device__ float g_x1 [(size_t)ROWS * CH];
__device__ __half g_hb  [(size_t)ROWS * CH];
__device__ __half g_qkvh[(size_t)ROWS * C3];
__device__ __half g_attb[(size_t)ROWS * CH];
__device__ __half g_mlph[(size_t)ROWS * HFDIM];
__device__ __half g_wqkv[(size_t)C3 * CH];
__device__ __half g_wproj[(size_t)CH * CH];
__device__ __half g_wfc1[(size_t)HFDIM * CH];
__device__ __half g_wfc2[(size_t)CH * HFDIM];

// ---------------------------------------------------------------------------
// PTX helpers
// ---------------------------------------------------------------------------
__device__ __forceinline__ uint32_t smem_to_u32(const void* p) {
    uint32_t a;
    asm("{ .reg .u64 t; cvta.to.shared.u64 t, %1; cvt.u32.u64 %0, t; }"
        : "=r"(a) : "l"(p));
    return a;
}

#define MBARRIER_INIT(addr, cnt) \
    asm volatile("mbarrier.init.shared.b64 [%0], %1;" :: "r"((uint32_t)(addr)), "r"((uint32_t)(cnt)) : "memory")

#define MBARRIER_ARRIVE(addr) \
    asm volatile("mbarrier.arrive.shared.b64 _, [%0];" :: "r"((uint32_t)(addr)) : "memory")

#define MBARRIER_EXPECT_TX(addr, bytes) \
    asm volatile("mbarrier.arrive.expect_tx.shared.b64 _, [%0], %1;" :: "r"((uint32_t)(addr)), "r"((uint32_t)(bytes)) : "memory")

#define MBARRIER_WAIT_PARITY(mbar_smem_addr, phase_parity) do { \
    uint32_t _mbar = (uint32_t)(mbar_smem_addr); \
    uint32_t _parity = (uint32_t)(phase_parity); \
    uint32_t _done; \
    asm volatile( \
        "{\n\t.reg .pred p;\n\t" \
        "mbarrier.try_wait.parity.acquire.cta.shared::cta.b64 p, [%1], %2;\n\t" \
        "selp.b32 %0, 1, 0, p;\n\t}" \
        : "=r"(_done) : "r"(_mbar), "r"(_parity) : "memory"); \
    if (!_done) { \
        asm volatile( \
            "{\n\t.reg .pred P1;\n\t" \
            "WAIT_LOOP_%=:\n\t" \
            "mbarrier.try_wait.parity.acquire.cta.shared::cta.b64 P1, [%0], %1, 0x989680;\n\t" \
            "@P1 bra.uni WAIT_DONE_%=;\n\t" \
            "bra.uni WAIT_LOOP_%=;\n\t" \
            "WAIT_DONE_%=:\n\t}" \
            :: "r"(_mbar), "r"(_parity) : "memory"); \
    } \
} while(0)

#define MBARRIER_WAIT_PARITY_RELAXED(mbar_smem_addr, phase_parity) do { \
    uint32_t _mbar = (uint32_t)(mbar_smem_addr); \
    uint32_t _parity = (uint32_t)(phase_parity); \
    uint32_t _done; \
    asm volatile( \
        "{\n\t.reg .pred p;\n\t" \
        "mbarrier.try_wait.parity.relaxed.cta.shared::cta.b64 p, [%1], %2, 0x989680;\n\t" \
        "selp.b32 %0, 1, 0, p;\n\t}" \
        : "=r"(_done) : "r"(_mbar), "r"(_parity) : "memory"); \
    if (!_done) { \
        asm volatile( \
            "{\n\t.reg .pred P1;\n\t" \
            "WAIT_LOOP_%=:\n\t" \
            "mbarrier.try_wait.parity.relaxed.cta.shared::cta.b64 P1, [%0], %1, 0x989680;\n\t" \
            "@P1 bra.uni WAIT_DONE_%=;\n\t" \
            "bra.uni WAIT_LOOP_%=;\n\t" \
            "WAIT_DONE_%=:\n\t}" \
            :: "r"(_mbar), "r"(_parity) : "memory"); \
    } \
} while(0)

__device__ __forceinline__ void ldsm_x4(uint32_t* r, uint32_t addr) {
    asm volatile("ldmatrix.sync.aligned.m8n8.x4.shared.b16 {%0,%1,%2,%3}, [%4];"
        : "=r"(r[0]), "=r"(r[1]), "=r"(r[2]), "=r"(r[3]) : "r"(addr));
}
__device__ __forceinline__ void ldsm_x4_t(uint32_t* r, uint32_t addr) {
    asm volatile("ldmatrix.sync.aligned.m8n8.x4.trans.shared.b16 {%0,%1,%2,%3}, [%4];"
        : "=r"(r[0]), "=r"(r[1]), "=r"(r[2]), "=r"(r[3]) : "r"(addr));
}

__device__ __forceinline__ void mma_f16(float* c, const uint32_t* a, uint32_t b0, uint32_t b1) {
    asm volatile(
        "mma.sync.aligned.m16n8k16.row.col.f32.f16.f16.f32 "
        "{%0,%1,%2,%3}, {%4,%5,%6,%7}, {%8,%9}, {%0,%1,%2,%3};"
        : "+f"(c[0]), "+f"(c[1]), "+f"(c[2]), "+f"(c[3])
        : "r"(a[0]), "r"(a[1]), "r"(a[2]), "r"(a[3]), "r"(b0), "r"(b1));
}

// pack (lo, hi) floats into f16x2
__device__ __forceinline__ uint32_t pack_f16(float lo, float hi) {
    uint32_t d;
    asm("cvt.rn.f16x2.f32 %0, %1, %2;" : "=r"(d) : "f"(hi), "f"(lo));
    return d;
}

// single-MUFU 2^x
__device__ __forceinline__ float ex2(float x) {
    float y;
    asm("ex2.approx.ftz.f32 %0, %1;" : "=f"(y) : "f"(x));
    return y;
}

__device__ __forceinline__ void cpasync16(uint32_t dst, const void* src) {
    asm volatile("cp.async.cg.shared.global [%0], [%1], 16;" :: "r"(dst), "l"(src) : "memory");
}
#define CPASYNC_COMMIT() asm volatile("cp.async.commit_group;" ::: "memory")
#define CPASYNC_WAIT0()  asm volatile("cp.async.wait_group 0;" ::: "memory")

// ---------------------------------------------------------------------------
// 0) Merged: fp32->fp16 weight conversion + ada = silu(c) @ ada_w^T + ada_b
// ---------------------------------------------------------------------------
#define CVT_N1 (C3 * CH / 4)
#define CVT_N2 (CVT_N1 + CH * CH / 4)
#define CVT_N3 (CVT_N2 + HFDIM * CH / 4)
#define CVT_N4 (CVT_N3 + CH * HFDIM / 4)
#define CVT_BLOCKS ((CVT_N4 + 255) / 256)
#define ADA_BLOCKS (BATCH * (C6 / 8))          // 8 x 576

__global__ __launch_bounds__(256) void cvt_ada_kernel(
    const float* __restrict__ s0, const float* __restrict__ s1,
    const float* __restrict__ s2, const float* __restrict__ s3,
    const float* __restrict__ c,
    const float* __restrict__ ada_w,
    const float* __restrict__ ada_b)
{
    __shared__ float sc[CH];
    int bid = blockIdx.x;
    if (bid < CVT_BLOCKS) {
        int i = bid * 256 + threadIdx.x;
        if (i >= CVT_N4) return;
        const float* src; __half* dst; int off;
        if (i < CVT_N1)      { src = s0; dst = g_wqkv;  off = i; }
        else if (i < CVT_N2) { src = s1; dst = g_wproj; off = i - CVT_N1; }
        else if (i < CVT_N3) { src = s2; dst = g_wfc1;  off = i - CVT_N2; }
        else                 { src = s3; dst = g_wfc2;  off = i - CVT_N3; }
        float4 v = *(const float4*)(src + (size_t)off * 4);
        uint32_t* d = (uint32_t*)dst + (size_t)off * 2;
        d[0] = pack_f16(v.x, v.y);
        d[1] = pack_f16(v.z, v.w);
        return;
    }
    // ada part
    int abid = bid - CVT_BLOCKS;       // 0 .. ADA_BLOCKS-1
    int b = abid / (C6 / 8);
    int jb = abid % (C6 / 8);
    for (int k = threadIdx.x; k < CH; k += 256) {
        float v = c[b * CH + k];
        sc[k] = v / (1.f + expf(-v));
    }
    __syncthreads();
    int warp = threadIdx.x >> 5, lane = threadIdx.x & 31;
    int j = jb * 8 + warp;
    const float* w = ada_w + (size_t)j * CH;
    float s = 0.f;
    for (int k = lane; k < CH; k += 32) s += sc[k] * w[k];
#pragma unroll
    for (int o = 16; o; o >>= 1) s += __shfl_xor_sync(0xffffffffu, s, o);
    if (lane == 0) g_ada[b * C6 + j] = s + ada_b[j];
}

// ---------------------------------------------------------------------------
// 2) h = LN(x) * (1 + sc[b]) + sh[b]   -> fp16.  One warp per row.
// ---------------------------------------------------------------------------
__global__ __launch_bounds__(256) void ln_mod_kernel(
    const float* __restrict__ x, int sh_off, int sc_off,
    __half* __restrict__ out)
{
    int r = blockIdx.x * 8 + (threadIdx.x >> 5);
    int lane = threadIdx.x & 31;
    int b = r >> 10;
    const float* xr = x + (size_t)r * CH;

    float4 v[6];
    float s = 0.f, ss = 0.f;
#pragma unroll
    for (int u = 0; u < 6; u++) {
        v[u] = *(const float4*)(xr + lane * 4 + u * 128);
        s  += v[u].x + v[u].y + v[u].z + v[u].w;
        ss += v[u].x * v[u].x + v[u].y * v[u].y + v[u].z * v[u].z + v[u].w * v[u].w;
    }
#pragma unroll
    for (int o = 16; o; o >>= 1) {
        s  += __shfl_xor_sync(0xffffffffu, s,  o);
        ss += __shfl_xor_sync(0xffffffffu, ss, o);
    }
    float mu  = s  * (1.f / (float)CH);
    float var = ss * (1.f / (float)CH) - mu * mu;
    float rinv = rsqrtf(var + 1e-6f);

    const float* sh  = g_ada + b * C6 + sh_off;
    const float* scm = g_ada + b * C6 + sc_off;
    uint32_t* orow = (uint32_t*)(out + (size_t)r * CH);
#pragma unroll
    for (int u = 0; u < 6; u++) {
        int i = lane * 4 + u * 128;
        float4 sh4  = *(const float4*)(sh + i);
        float4 sc4  = *(const float4*)(scm + i);
        float o0 = (v[u].x - mu) * rinv * (1.f + sc4.x) + sh4.x;
        float o1 = (v[u].y - mu) * rinv * (1.f + sc4.y) + sh4.y;
        float o2 = (v[u].z - mu) * rinv * (1.f + sc4.z) + sh4.z;
        float o3 = (v[u].w - mu) * rinv * (1.f + sc4.w) + sh4.w;
        orow[(i >> 1) + 0] = pack_f16(o0, o1);
        orow[(i >> 1) + 1] = pack_f16(o2, o3);
    }
}

// ---------------------------------------------------------------------------
// 3) TMA + mma.sync fp16 GEMM: 128x128 tile, 3-stage pipeline, 2 CTAs/SM.
//    288 threads: warps 0-7 compute (64x32 each), warp 8 = TMA producer.
//    A-fragments register double-buffered across k16 steps.
//    EPI: 0 = bias -> fp16; 1 = bias+GELU -> fp16; 2 = resid+gate -> fp32
// ---------------------------------------------------------------------------
#define GSTAGES 3
#define STAGE_BYTES 32768            // A 16KB + B 16KB
#define GEMM_SMEM (1024 + GSTAGES * STAGE_BYTES)   // 99328

// swizzled address in [rows x 128B] SW128 tile, chunk = 16B unit
__device__ __forceinline__ uint32_t gsw(uint32_t base, int row, int chunk) {
    return base + row * 128 + ((chunk ^ (row & 7)) << 4);
}

template <int EPI>
__global__ __launch_bounds__(288, 2) void tc_gemm_kernel(
    const __grid_constant__ CUtensorMap tmA,
    const __grid_constant__ CUtensorMap tmB,
    const float* __restrict__ bias,
    const float* __restrict__ resid,
    const float* __restrict__ gate,
    void* __restrict__ CoutV,
    int Nc, int K)
{
    extern __shared__ __align__(1024) char smem[];
    uint32_t sbase = smem_to_u32(smem);
    const int t = threadIdx.x, wid = t >> 5, lane = t & 31;
    const int m0 = blockIdx.y * 128, n0 = blockIdx.x * 128;
    const int KT = K / 64;

    const uint32_t mb_full  = sbase + 0;
    const uint32_t mb_empty = sbase + 64;
    const uint32_t stg = sbase + 1024;

    if (t == 0) {
#pragma unroll
        for (int s = 0; s < GSTAGES; s++) {
            MBARRIER_INIT(mb_full  + 8 * s, 1);
            MBARRIER_INIT(mb_empty + 8 * s, 8);
        }
    }
    __syncthreads();

    if (wid == 8) {
        if (lane == 0) {
            asm volatile("prefetch.tensormap [%0];" :: "l"(&tmA));
            asm volatile("prefetch.tensormap [%0];" :: "l"(&tmB));
            int npro = KT < GSTAGES ? KT : GSTAGES;
            for (int tt = 0; tt < npro; tt++) {
                uint32_t fm = mb_full + 8 * tt;
                uint32_t aA = stg + tt * STAGE_BYTES;
                MBARRIER_EXPECT_TX(fm, STAGE_BYTES);
                int k0 = tt * 64;
                asm volatile(
                    "cp.async.bulk.tensor.2d.shared::cta.global.tile.mbarrier::complete_tx::bytes "
                    "[%0], [%1, {%2, %3}], [%4];"
                    :: "r"(aA), "l"(&tmA), "r"(k0), "r"(m0), "r"(fm) : "memory");
                asm volatile(
                    "cp.async.bulk.tensor.2d.shared::cta.global.tile.mbarrier::complete_tx::bytes "
                    "[%0], [%1, {%2, %3}], [%4];"
                    :: "r"(aA + 16384), "l"(&tmB), "r"(k0), "r"(n0), "r"(fm) : "memory");
            }
            int slot = 0, ph = 0;
            for (int tt = GSTAGES; tt < KT; tt++) {
                MBARRIER_WAIT_PARITY_RELAXED(mb_empty + 8 * slot, ph);
                uint32_t fm = mb_full + 8 * slot;
                uint32_t aA = stg + slot * STAGE_BYTES;
                MBARRIER_EXPECT_TX(fm, STAGE_BYTES);
                int k0 = tt * 64;
                asm volatile(
                    "cp.async.bulk.tensor.2d.shared::cta.global.tile.mbarrier::complete_tx::bytes "
                    "[%0], [%1, {%2, %3}], [%4];"
                    :: "r"(aA), "l"(&tmA), "r"(k0), "r"(m0), "r"(fm) : "memory");
                asm volatile(
                    "cp.async.bulk.tensor.2d.shared::cta.global.tile.mbarrier::complete_tx::bytes "
                    "[%0], [%1, {%2, %3}], [%4];"
                    :: "r"(aA + 16384), "l"(&tmB), "r"(k0), "r"(n0), "r"(fm) : "memory");
                if (++slot == GSTAGES) { slot = 0; ph ^= 1; }
            }
        }
        return;
    }

    const int wm = wid >> 2;          // 0..1
    const int wn = wid & 3;           // 0..3
    const int g   = lane >> 2;
    const int ctg = lane & 3;
    const int lrow = (lane & 7) + 8 * ((lane >> 3) & 1);
    const int lch  = lane >> 4;

    float acc[4][4][4];
#pragma unroll
    for (int im = 0; im < 4; im++)
#pragma unroll
        for (int in = 0; in < 4; in++)
#pragma unroll
            for (int r = 0; r < 4; r++) acc[im][in][r] = 0.f;

    uint32_t afr[2][4][4];
    int slot = 0, ph = 0;
    for (int tt = 0; tt < KT; tt++) {
        MBARRIER_WAIT_PARITY(mb_full + 8 * slot, ph);
        const uint32_t At = stg + slot * STAGE_BYTES;
        const uint32_t Bt = At + 16384;

        // preload A fragments for k16 step 0
#pragma unroll
        for (int im = 0; im < 4; im++)
            ldsm_x4(afr[0][im], gsw(At, wm * 64 + im * 16 + lrow, lch));

#pragma unroll
        for (int s = 0; s < 4; s++) {            // k16 steps
            const int cur = s & 1;
            // prefetch next step's A fragments (hidden under this step's MMAs)
            if (s < 3) {
                const int kcn = 2 * (s + 1);
#pragma unroll
                for (int im = 0; im < 4; im++)
                    ldsm_x4(afr[cur ^ 1][im], gsw(At, wm * 64 + im * 16 + lrow, kcn + lch));
            }
            const int kc = 2 * s;
            uint32_t bfr[4][2];
#pragma unroll
            for (int jn = 0; jn < 2; jn++) {
                uint32_t q[4];
                ldsm_x4(q, gsw(Bt, wn * 32 + jn * 16 + lrow, kc + lch));
                bfr[2 * jn][0]     = q[0]; bfr[2 * jn][1]     = q[2];
                bfr[2 * jn + 1][0] = q[1]; bfr[2 * jn + 1][1] = q[3];
            }
#pragma unroll
            for (int im = 0; im < 4; im++)
#pragma unroll
                for (int in = 0; in < 4; in++)
                    mma_f16(acc[im][in], afr[cur][im], bfr[in][0], bfr[in][1]);
        }

        if (lane == 0) MBARRIER_ARRIVE(mb_empty + 8 * slot);
        if (++slot == GSTAGES) { slot = 0; ph ^= 1; }
    }

    // epilogue
    const int bidx = m0 >> 10;        // tiles never straddle a batch
    const int mB = m0 + wm * 64;
    const int nB = n0 + wn * 32;
#pragma unroll
    for (int im = 0; im < 4; im++) {
        int r = mB + im * 16 + g;
#pragma unroll
        for (int in = 0; in < 4; in++) {
            int n = nB + in * 8 + 2 * ctg;
            float b0 = bias[n], b1 = bias[n + 1];
#pragma unroll
            for (int half = 0; half < 2; half++) {
                int m = r + half * 8;
                float v0 = acc[im][in][2 * half + 0] + b0;
                float v1 = acc[im][in][2 * half + 1] + b1;
                if (EPI == 1) {
                    v0 = 0.5f * v0 * (1.f + erff(v0 * 0.70710678118654752f));
                    v1 = 0.5f * v1 * (1.f + erff(v1 * 0.70710678118654752f));
                }
                if (EPI == 2) {
                    const float2 rr = *(const float2*)&resid[(size_t)m * Nc + n];
                    float g0 = gate[bidx * C6 + n], g1 = gate[bidx * C6 + n + 1];
                    v0 = rr.x + g0 * v0;
                    v1 = rr.y + g1 * v1;
                    *(float2*)&((float*)CoutV)[(size_t)m * Nc + n] = make_float2(v0, v1);
                } else {
                    ((uint32_t*)CoutV)[((size_t)m * Nc + n) >> 1] = pack_f16(v0, v1);
                }
            }
        }
    }
}

// ---------------------------------------------------------------------------
// 4) fp16 flash attention: 128 q-rows per CTA (8 warps), K/V 64-row tiles
//    double-buffered via cp.async, P in registers, exp2 softmax (MUFU).
// ---------------------------------------------------------------------------
#define AT_WB 144                        // tile row stride in bytes
#define AT_TILE_B (64 * AT_WB)           // K/V tile: 64 rows
#define AQ_TILE_B (128 * AT_WB)          // Q tile: 128 rows
#define ATT_SMEM (AQ_TILE_B + 4 * AT_TILE_B)   // 55296

__global__ __launch_bounds__(256, 2) void attn_tc_kernel(
    const __half* __restrict__ qkv, __half* __restrict__ out)
{
    extern __shared__ __align__(16) char as[];
    const uint32_t Qb = smem_to_u32(as);
    const uint32_t Kb = Qb + AQ_TILE_B;
    const uint32_t Vb = Kb + 2 * AT_TILE_B;

    const int b = blockIdx.z, h = blockIdx.y;
    const int q0 = blockIdx.x * 128;
    const int t = threadIdx.x, wq = t >> 5, lane = t & 31;
    const int g = lane >> 2, ctg = lane & 3;
    const int lrow = (lane & 7) + 8 * ((lane >> 3) & 1);
    const int lch  = lane >> 4;

    const __half* qb = qkv + (size_t)(b * SEQ) * C3 + h * HDIM;
    const __half* kb = qb + CH;
    const __half* vb = qb + 2 * CH;

    const float cs = 0.18033688f;        // 0.125 * log2(e)

    // Q tile: 128 rows x 8 chunks = 1024 chunks, 4 per thread
#pragma unroll
    for (int u = 0; u < 4; u++) {
        int i = t + u * 256;
        int r = i >> 3, c = i & 7;
        cpasync16(Qb + (uint32_t)(r * AT_WB + c * 16),
                  qb + (size_t)(q0 + r) * C3 + c * 8);
    }
    // K/V tile 0: 64 rows x 8 chunks = 512 chunks, 2 per thread each
#pragma unroll
    for (int u = 0; u < 2; u++) {
        int i = t + u * 256;
        int r = i >> 3, c = i & 7;
        uint32_t so = (uint32_t)(r * AT_WB + c * 16);
        cpasync16(Kb + so, kb + (size_t)r * C3 + c * 8);
        cpasync16(Vb + so, vb + (size_t)r * C3 + c * 8);
    }
    CPASYNC_COMMIT();

    float m0 = -1e30f, m1 = -1e30f, l0 = 0.f, l1 = 0.f;
    float oac[8][4];
#pragma unroll
    for (int in = 0; in < 8; in++)
#pragma unroll
        for (int r = 0; r < 4; r++) oac[in][r] = 0.f;

    uint32_t qf[4][4];

    for (int kt = 0; kt < 16; kt++) {
        CPASYNC_WAIT0();
        __syncthreads();
        if (kt == 0) {
#pragma unroll
            for (int kk = 0; kk < 4; kk++)
                ldsm_x4(qf[kk], Qb + (wq * 16 + lrow) * AT_WB + (2 * kk + lch) * 16);
        }
        if (kt + 1 < 16) {
            int nb = (kt + 1) & 1;
            int kr0 = (kt + 1) * 64;
            uint32_t kd = Kb + nb * AT_TILE_B;
            uint32_t vd = Vb + nb * AT_TILE_B;
#pragma unroll
            for (int u = 0; u < 2; u++) {
                int i = t + u * 256;
                int r = i >> 3, c = i & 7;
                uint32_t so = (uint32_t)(r * AT_WB + c * 16);
                cpasync16(kd + so, kb + (size_t)(kr0 + r) * C3 + c * 8);
                cpasync16(vd + so, vb + (size_t)(kr0 + r) * C3 + c * 8);
            }
            CPASYNC_COMMIT();
        }

        const uint32_t Kt = Kb + (kt & 1) * AT_TILE_B;
        const uint32_t Vt = Vb + (kt & 1) * AT_TILE_B;

        // S = Q @ K^T (raw, scale folded into softmax)
        float sac[8][4];
#pragma unroll
        for (int in = 0; in < 8; in++)
#pragma unroll
            for (int r = 0; r < 4; r++) sac[in][r] = 0.f;

#pragma unroll
        for (int kk = 0; kk < 4; kk++) {
            const int kc = 2 * kk;
#pragma unroll
            for (int jn = 0; jn < 4; jn++) {
                uint32_t q[4];
                ldsm_x4(q, Kt + (jn * 16 + lrow) * AT_WB + (kc + lch) * 16);
                mma_f16(sac[2 * jn],     qf[kk], q[0], q[2]);
                mma_f16(sac[2 * jn + 1], qf[kk], q[1], q[3]);
            }
        }

        // online softmax in log2 domain (rows g, g+8)
        float mx0 = -1e30f, mx1 = -1e30f;
#pragma unroll
        for (int in = 0; in < 8; in++) {
            mx0 = fmaxf(mx0, fmaxf(sac[in][0], sac[in][1]));
            mx1 = fmaxf(mx1, fmaxf(sac[in][2], sac[in][3]));
        }
        mx0 = fmaxf(mx0, __shfl_xor_sync(0xffffffffu, mx0, 1));
        mx0 = fmaxf(mx0, __shfl_xor_sync(0xffffffffu, mx0, 2));
        mx1 = fmaxf(mx1, __shfl_xor_sync(0xffffffffu, mx1, 1));
        mx1 = fmaxf(mx1, __shfl_xor_sync(0xffffffffu, mx1, 2));

        float mn0 = fmaxf(m0, mx0 * cs), mn1 = fmaxf(m1, mx1 * cs);
        float a0 = ex2(m0 - mn0), a1 = ex2(m1 - mn1);
        float s0 = 0.f, s1 = 0.f;
#pragma unroll
        for (int in = 0; in < 8; in++) {
            sac[in][0] = ex2(fmaf(sac[in][0], cs, -mn0));
            sac[in][1] = ex2(fmaf(sac[in][1], cs, -mn0));
            sac[in][2] = ex2(fmaf(sac[in][2], cs, -mn1));
            sac[in][3] = ex2(fmaf(sac[in][3], cs, -mn1));
            s0 += sac[in][0] + sac[in][1];
            s1 += sac[in][2] + sac[in][3];
        }
        s0 += __shfl_xor_sync(0xffffffffu, s0, 1);
        s0 += __shfl_xor_sync(0xffffffffu, s0, 2);
        s1 += __shfl_xor_sync(0xffffffffu, s1, 1);
        s1 += __shfl_xor_sync(0xffffffffu, s1, 2);
        l0 = l0 * a0 + s0; m0 = mn0;
        l1 = l1 * a1 + s1; m1 = mn1;
#pragma unroll
        for (int in = 0; in < 8; in++) {
            oac[in][0] *= a0; oac[in][1] *= a0;
            oac[in][2] *= a1; oac[in][3] *= a1;
        }

        // O += P @ V (P packed to fp16 in registers)
#pragma unroll
        for (int kk = 0; kk < 4; kk++) {
            uint32_t pf[4];
            pf[0] = pack_f16(sac[2 * kk][0],     sac[2 * kk][1]);
            pf[1] = pack_f16(sac[2 * kk][2],     sac[2 * kk][3]);
            pf[2] = pack_f16(sac[2 * kk + 1][0], sac[2 * kk + 1][1]);
            pf[3] = pack_f16(sac[2 * kk + 1][2], sac[2 * kk + 1][3]);
            const int vrow = 16 * kk + (lane & 7) + 8 * (lane >> 4);
#pragma unroll
            for (int jn = 0; jn < 4; jn++) {
                uint32_t q[4];
                ldsm_x4_t(q, Vt + vrow * AT_WB + (2 * jn + ((lane >> 3) & 1)) * 16);
                mma_f16(oac[2 * jn],     pf, q[0], q[2]);
                mma_f16(oac[2 * jn + 1], pf, q[1], q[3]);
            }
        }
        // no bottom barrier needed: next iteration's wait+sync orders buffer reuse
    }

    // write O (fp16)
    float inv0 = 1.f / l0, inv1 = 1.f / l1;
    int row0 = b * SEQ + q0 + wq * 16 + g;
    uint32_t* o32 = (uint32_t*)out;
#pragma unroll
    for (int in = 0; in < 8; in++) {
        int col = h * HDIM + in * 8 + 2 * ctg;
        o32[((size_t)row0 * CH + col) >> 1] =
            pack_f16(oac[in][0] * inv0, oac[in][1] * inv0);
        o32[((size_t)(row0 + 8) * CH + col) >> 1] =
            pack_f16(oac[in][2] * inv1, oac[in][3] * inv1);
    }
}

// ---------------------------------------------------------------------------
// Host: tensormap construction
// ---------------------------------------------------------------------------
typedef CUresult (*PFN_tmEncode)(
    CUtensorMap*, CUtensorMapDataType, cuuint32_t, void*,
    const cuuint64_t*, const cuuint64_t*, const cuuint32_t*, const cuuint32_t*,
    CUtensorMapInterleave, CUtensorMapSwizzle, CUtensorMapL2promotion,
    CUtensorMapFloatOOBfill);

static PFN_tmEncode get_tm_encode() {
    void* fn = nullptr;
#if CUDART_VERSION >= 12050
    cudaDriverEntryPointQueryResult qr;
    cudaGetDriverEntryPointByVersion("cuTensorMapEncodeTiled", &fn, 12000,
                                     cudaEnableDefault, &qr);
#else
    cudaDriverEntryPointQueryResult qr;
    cudaGetDriverEntryPoint("cuTensorMapEncodeTiled", &fn, cudaEnableDefault, &qr);
#endif
    return (PFN_tmEncode)fn;
}

static void make_tm_f16(PFN_tmEncode enc, CUtensorMap* tm, const void* p, int K, int M) {
    cuuint64_t dims[2]    = {(cuuint64_t)K, (cuuint64_t)M};
    cuuint64_t strides[1] = {(cuuint64_t)K * 2};
    cuuint32_t box[2]     = {64u, 128u};
    cuuint32_t es[2]      = {1u, 1u};
    enc(tm, CU_TENSOR_MAP_DATA_TYPE_FLOAT16, 2, (void*)p, dims, strides, box, es,
        CU_TENSOR_MAP_INTERLEAVE_NONE, CU_TENSOR_MAP_SWIZZLE_128B,
        CU_TENSOR_MAP_L2_PROMOTION_L2_128B, CU_TENSOR_MAP_FLOAT_OOB_FILL_NONE);
}

// ---------------------------------------------------------------------------
// Launch
// ---------------------------------------------------------------------------
extern "C" void kernel_launch(void* const* d_in, const int* in_sizes, int n_in,
                              void* d_out, int out_size)
{
    const float* x      = (const float*)d_in[0];
    const float* c      = (const float*)d_in[1];
    const float* qkv_w  = (const float*)d_in[2];
    const float* qkv_b  = (const float*)d_in[3];
    const float* proj_w = (const float*)d_in[4];
    const float* proj_b = (const float*)d_in[5];
    const float* fc1_w  = (const float*)d_in[6];
    const float* fc1_b  = (const float*)d_in[7];
    const float* fc2_w  = (const float*)d_in[8];
    const float* fc2_b  = (const float*)d_in[9];
    const float* ada_w  = (const float*)d_in[10];
    const float* ada_b  = (const float*)d_in[11];
    float* out = (float*)d_out;

    float *p_ada, *p_x1;
    __half *p_hb, *p_qkvh, *p_attb, *p_mlph, *p_wqkv, *p_wproj, *p_wfc1, *p_wfc2;
    cudaGetSymbolAddress((void**)&p_ada,   g_ada);
    cudaGetSymbolAddress((void**)&p_x1,    g_x1);
    cudaGetSymbolAddress((void**)&p_hb,    g_hb);
    cudaGetSymbolAddress((void**)&p_qkvh,  g_qkvh);
    cudaGetSymbolAddress((void**)&p_attb,  g_attb);
    cudaGetSymbolAddress((void**)&p_mlph,  g_mlph);
    cudaGetSymbolAddress((void**)&p_wqkv,  g_wqkv);
    cudaGetSymbolAddress((void**)&p_wproj, g_wproj);
    cudaGetSymbolAddress((void**)&p_wfc1,  g_wfc1);
    cudaGetSymbolAddress((void**)&p_wfc2,  g_wfc2);

    PFN_tmEncode enc = get_tm_encode();
    alignas(64) CUtensorMap tm_h, tm_att, tm_mlp, tm_qkvw, tm_projw, tm_fc1w, tm_fc2w;
    make_tm_f16(enc, &tm_h,     p_hb,    CH,    ROWS);
    make_tm_f16(enc, &tm_att,   p_attb,  CH,    ROWS);
    make_tm_f16(enc, &tm_mlp,   p_mlph,  HFDIM, ROWS);
    make_tm_f16(enc, &tm_qkvw,  p_wqkv,  CH,    C3);
    make_tm_f16(enc, &tm_projw, p_wproj, CH,    CH);
    make_tm_f16(enc, &tm_fc1w,  p_wfc1,  CH,    HFDIM);
    make_tm_f16(enc, &tm_fc2w,  p_wfc2,  HFDIM, CH);

    cudaFuncSetAttribute((const void*)tc_gemm_kernel<0>, cudaFuncAttributeMaxDynamicSharedMemorySize, GEMM_SMEM);
    cudaFuncSetAttribute((const void*)tc_gemm_kernel<1>, cudaFuncAttributeMaxDynamicSharedMemorySize, GEMM_SMEM);
    cudaFuncSetAttribute((const void*)tc_gemm_kernel<2>, cudaFuncAttributeMaxDynamicSharedMemorySize, GEMM_SMEM);
    cudaFuncSetAttribute((const void*)attn_tc_kernel, cudaFuncAttributeMaxDynamicSharedMemorySize, ATT_SMEM);

    // 0) weight conversion + adaLN parameters (one launch)
    cvt_ada_kernel<<<CVT_BLOCKS + ADA_BLOCKS, 256>>>(
        qkv_w, proj_w, fc1_w, fc2_w, c, ada_w, ada_b);

    // 2) h = modulate(LN(x), sh_msa, sc_msa) -> fp16
    ln_mod_kernel<<<ROWS / 8, 256>>>(x, 0, 768, p_hb);

    // 3) qkv = h @ qkv_w^T + qkv_b -> fp16
    tc_gemm_kernel<0><<<dim3(C3 / 128, ROWS / 128), 288, GEMM_SMEM>>>(
        tm_h, tm_qkvw, qkv_b, nullptr, nullptr, p_qkvh, C3, CH);

    // 4) attention -> fp16
    attn_tc_kernel<<<dim3(SEQ / 128, NHEAD, BATCH), 256, ATT_SMEM>>>(p_qkvh, p_attb);

    // 5) x1 = x + g_msa * (attn @ proj_w^T + proj_b) -> fp32
    tc_gemm_kernel<2><<<dim3(CH / 128, ROWS / 128), 288, GEMM_SMEM>>>(
        tm_att, tm_projw, proj_b, x, p_ada + 1536, p_x1, CH, CH);

    // 6) h = modulate(LN(x1), sh_mlp, sc_mlp) -> fp16
    ln_mod_kernel<<<ROWS / 8, 256>>>(p_x1, 2304, 3072, p_hb);

    // 7) mlp_hidden = gelu(h @ fc1_w^T + fc1_b) -> fp16
    tc_gemm_kernel<1><<<dim3(HFDIM / 128, ROWS / 128), 288, GEMM_SMEM>>>(
        tm_h, tm_fc1w, fc1_b, nullptr, nullptr, p_mlph, HFDIM, CH);

    // 8) out = x1 + g_mlp * (mlp_hidden @ fc2_w^T + fc2_b) -> fp32
    tc_gemm_kernel<2><<<dim3(CH / 128, ROWS / 128), 288, GEMM_SMEM>>>(
        tm_mlp, tm_fc2w, fc2_b, p_x1, p_ada + 3840, out, CH, HFDIM);
}